// round 11
// baseline (speedup 1.0000x reference)
#include <cuda_runtime.h>
#include <cstdint>

// Problem: input [B=128, C=2, H=512, W=512] fp32.
// out[:,0] = inclusive cumsum along x (contiguous axis)
// out[:,1] = inclusive cumsum along y (stride-W axis)
//
// One fused kernel, all blocks short-lived and bandwidth-bound:
//  x-role (8192 blocks): one warp per row, float4 warp-scan.
//  y-role (4096 blocks): 512x16 tile staged through smem with a per-segment
//    16-float skew (segment stride 528 ≡ 16 mod 32 banks) so the smem scan
//    phase is bank-conflict-free. Load/store phases use identical
//    float4-coalesced mappings. Streaming cache hints (__ldcs/__stcs)
//    since every byte is touched exactly once.
// Interleaved bid%3==0 -> y so both traffic types share every wave.

#define Bn 128
#define Wn 512
#define TCOLS 16                    // tile width (columns)
#define TSEG 32                     // rows per scan segment
#define NSEG 16                     // 512 / 32
#define SEG_STRIDE 528              // floats per segment (512 + 16 skew)
#define TILE_FLOATS (NSEG * SEG_STRIDE)   // 8448 floats = 33 KB
#define Y_BLOCKS 4096               // 128 images * (512/16) col-tiles
#define X_BLOCKS 8192               // 65536 rows / 8 warps
#define GRID_BLOCKS (Y_BLOCKS + X_BLOCKS)

// float4 index of row r, group 0, in the skewed tile
__device__ __forceinline__ unsigned trow4(unsigned r) {
    return (r >> 5) * (SEG_STRIDE / 4) + (r & 31u) * 4u;
}

// ---------------------------------------------------------------------------
// x-role: one warp per row of channel 0.
// ---------------------------------------------------------------------------
__device__ __forceinline__ void do_scan_x(const float* __restrict__ in,
                                          float* __restrict__ out,
                                          unsigned xbid) {
    const unsigned gwarp = xbid * 8u + (threadIdx.x >> 5);   // 0..65535
    const unsigned lane  = threadIdx.x & 31u;

    const unsigned b = gwarp >> 9;
    const unsigned y = gwarp & 511u;

    const size_t base = ((size_t)(b * 2u + 0u) * Wn + y) * Wn;  // channel 0
    const float4* __restrict__ in4  = (const float4*)(in + base);
    float4* __restrict__       out4 = (float4*)(out + base);

    float carry = 0.0f;
#pragma unroll
    for (int it = 0; it < 4; ++it) {
        float4 v = __ldcs(&in4[it * 32 + lane]);

        float s0 = v.x;
        float s1 = s0 + v.y;
        float s2 = s1 + v.z;
        float s3 = s2 + v.w;

        float incl = s3;
#pragma unroll
        for (int off = 1; off < 32; off <<= 1) {
            float n = __shfl_up_sync(0xffffffffu, incl, off);
            if (lane >= (unsigned)off) incl += n;
        }
        float excl = incl - s3 + carry;

        float4 o;
        o.x = s0 + excl;
        o.y = s1 + excl;
        o.z = s2 + excl;
        o.w = s3 + excl;
        __stcs(&out4[it * 32 + lane], o);

        carry += __shfl_sync(0xffffffffu, incl, 31);
    }
}

// ---------------------------------------------------------------------------
// y-role: 512x16 tile of channel 1 through skewed smem.
// ---------------------------------------------------------------------------
__device__ __forceinline__ void do_scan_y(const float* __restrict__ in,
                                          float* __restrict__ out,
                                          unsigned ybid,
                                          float* __restrict__ tile,
                                          float* __restrict__ spine,
                                          float* __restrict__ pre) {
    const unsigned tid = threadIdx.x;
    const unsigned b   = ybid >> 5;          // image (32 col-tiles per image)
    const unsigned tc  = ybid & 31u;         // col-tile
    const unsigned col0 = tc * TCOLS;

    const size_t base = ((size_t)(b * 2u + 1u) * Wn) * Wn + col0;  // ch1 row0

    const unsigned quad = tid & 3u;          // float4 within 16-col tile row
    const unsigned r0   = tid >> 2;          // 0..63
    float4* __restrict__ tile4 = (float4*)tile;

    // ---- load: 2048 float4s, 8 per thread, coalesced, independent ----
    {
        const float4* __restrict__ in4 = (const float4*)(in + base);
#pragma unroll
        for (int batch = 0; batch < 8; ++batch) {
            const unsigned row = batch * 64u + r0;
            tile4[trow4(row) + quad] = __ldcs(&in4[(size_t)row * 128u + quad]);
        }
    }
    __syncthreads();

    // ---- scan: thread (c, s) scans rows [s*32, s*32+32) of column c ----
    // Skewed addressing: addr = s*528 + i*16 + c. Segment stride 528 ≡ 16
    // (mod 32 banks) -> the warp's two half-warps hit disjoint bank halves.
    const unsigned c = tid & 15u;
    const unsigned s = tid >> 4;
    {
        float* __restrict__ p = tile + s * SEG_STRIDE + c;
        float acc = 0.0f;
#pragma unroll
        for (int i = 0; i < TSEG; ++i) {
            acc += p[i * TCOLS];
            p[i * TCOLS] = acc;            // in-place inclusive prefix
        }
        spine[s * TCOLS + c] = acc;        // segment total
    }
    __syncthreads();

    // ---- spine prefix: pre[s][c] = sum of spine[s2][c], s2 < s ----
    {
        float off = 0.0f;
        for (unsigned s2 = 0; s2 < s; ++s2)
            off += spine[s2 * TCOLS + c];
        pre[s * TCOLS + c] = off;
    }
    __syncthreads();

    // ---- store: same float4 mapping as load (fully coalesced) ----
    {
        float4* __restrict__ out4 = (float4*)(out + base);
        const float* __restrict__ prow = pre + quad * 4u;   // 4 col offsets
#pragma unroll
        for (int batch = 0; batch < 8; ++batch) {
            const unsigned row = batch * 64u + r0;
            const unsigned seg = row >> 5;                  // row / TSEG
            float4 v = tile4[trow4(row) + quad];
            v.x += prow[seg * TCOLS + 0];
            v.y += prow[seg * TCOLS + 1];
            v.z += prow[seg * TCOLS + 2];
            v.w += prow[seg * TCOLS + 3];
            __stcs(&out4[(size_t)row * 128u + quad], v);
        }
    }
}

__global__ void __launch_bounds__(256) fused_scan_kernel(const float* __restrict__ in,
                                                         float* __restrict__ out) {
    __shared__ float tile[TILE_FLOATS];      // 33 KB (skewed)
    __shared__ float spine[NSEG * TCOLS];    // 1 KB
    __shared__ float pre[NSEG * TCOLS];      // 1 KB

    const unsigned bid = blockIdx.x;
    const unsigned q = bid / 3u;
    if (bid == q * 3u) {
        do_scan_y(in, out, q, tile, spine, pre);     // 4096 y-tiles
    } else {
        do_scan_x(in, out, bid - q - 1u);            // 8192 x-blocks
    }
}

extern "C" void kernel_launch(void* const* d_in, const int* in_sizes, int n_in,
                              void* d_out, int out_size) {
    const float* in = (const float*)d_in[0];
    float* out = (float*)d_out;
    fused_scan_kernel<<<GRID_BLOCKS, 256>>>(in, out);
}